// round 13
// baseline (speedup 1.0000x reference)
#include <cuda_runtime.h>
#include <cuda_bf16.h>

// LSTM: B=32768, T=28, IN=28, H=8, NC=10. Gate order i,j,f,o. Forget bias 1.0.
// R13 = R12 + two latency fixes. R12 (weights-in-registers, 8 lanes/sample)
// killed the smem wall (L1 71%->20%) but went latency-bound (issue 18%):
//  (1) 36-deep RAW chains on 2 accumulators -> now 2-way split = 4 chains
//      of depth 18 (per-warp FFMA2 capability 1/cyc >= pipe rt 0.5);
//  (2) depth-3 shfl butterfly -> flat: v[p] = shfl_xor(h, p), 7 independent
//      shfls, depth 1 (m^p weight pre-permutation handles ordering).
// Zero LDS in hot loop; 5 exact activations/lane; forget bias folded.

#define BTOT 32768
#define TSTEPS 28
#define INDIM 28
#define HID 8
#define NCLS 10
#define BLK 128

typedef unsigned long long u64;

__device__ __forceinline__ u64 pack2(float x) {
    u64 r; unsigned xi = __float_as_uint(x);
    asm("mov.b64 %0, {%1, %1};" : "=l"(r) : "r"(xi));
    return r;
}

__device__ __forceinline__ u64 packab(float a, float b) {
    u64 r; unsigned ai = __float_as_uint(a), bi = __float_as_uint(b);
    asm("mov.b64 %0, {%1, %2};" : "=l"(r) : "r"(ai), "r"(bi));
    return r;
}

__device__ __forceinline__ u64 fma2(u64 a, u64 b, u64 c) {
    u64 d;
    asm("fma.rn.f32x2 %0, %1, %2, %3;" : "=l"(d) : "l"(a), "l"(b), "l"(c));
    return d;
}

__device__ __forceinline__ u64 add2(u64 a, u64 b) {
    u64 d;
    asm("add.rn.f32x2 %0, %1, %2;" : "=l"(d) : "l"(a), "l"(b));
    return d;
}

__device__ __forceinline__ void unpack2(u64 v, float& lo, float& hi) {
    unsigned a, b;
    asm("mov.b64 {%0, %1}, %2;" : "=r"(a), "=r"(b) : "l"(v));
    lo = __uint_as_float(a);
    hi = __uint_as_float(b);
}

__device__ __forceinline__ float sigf(float x) {
    float e = __expf(-x);
    return __fdividef(1.0f, 1.0f + e);
}

__device__ __forceinline__ float tanh_exact(float x) {
    // tanh(x) = 1 - 2/(e^{2x}+1). Overflow of e -> +1; underflow -> -1.
    float e = __expf(2.0f * x);
    return 1.0f - __fdividef(2.0f, e + 1.0f);
}

__global__ __launch_bounds__(BLK)
void lstm_kernel(const float* __restrict__ x,
                 const float* __restrict__ W,      // [36, 32] row-major
                 const float* __restrict__ bias,   // [32]
                 const float* __restrict__ ow,     // [8, 10]
                 const float* __restrict__ ob,     // [10]
                 float* __restrict__ out)          // [B, 10]
{
    __shared__ float sWraw[(INDIM + HID) * 32];   // 36 x 32, row-major staging
    __shared__ float sBr[32];
    __shared__ float sOW[HID * NCLS];
    __shared__ float sOB[NCLS];

    const int tid = threadIdx.x;
    for (int i = tid; i < (INDIM + HID) * 32; i += BLK) sWraw[i] = W[i];
    for (int i = tid; i < 32; i += BLK)          sBr[i] = bias[i];
    for (int i = tid; i < HID * NCLS; i += BLK)  sOW[i] = ow[i];
    for (int i = tid; i < NCLS; i += BLK)        sOB[i] = ob[i];
    __syncthreads();

    const int gtid   = blockIdx.x * BLK + tid;
    const int sample = gtid >> 3;     // 8 lanes per sample
    const int m      = gtid & 7;      // hidden unit owned by this lane

    // One-time register gather. Pair layout: (i_col, j_col) and (f_col, o_col).
    u64 wXij[INDIM], wXfo[INDIM];
#pragma unroll
    for (int k = 0; k < INDIM; k++) {
        const float* r = sWraw + k * 32;
        wXij[k] = packab(r[m],      r[8 + m]);
        wXfo[k] = packab(r[16 + m], r[24 + m]);
    }
    // h-row weights in shfl arrival order: position p delivers h[m^p].
    u64 wHij[HID], wHfo[HID];
#pragma unroll
    for (int p = 0; p < HID; p++) {
        const float* r = sWraw + (INDIM + (m ^ p)) * 32;
        wHij[p] = packab(r[m],      r[8 + m]);
        wHfo[p] = packab(r[16 + m], r[24 + m]);
    }
    const u64 bIJ = packab(sBr[m], sBr[8 + m]);
    const u64 bFO = packab(sBr[16 + m] + 1.0f, sBr[24 + m]);   // forget bias folded

    const float4* xp = (const float4*)(x + (size_t)sample * TSTEPS * INDIM);  // 7/step

    float c = 0.0f;
    float v[HID];                      // h in shfl order: v[p] = h[m^p]
#pragma unroll
    for (int p = 0; p < HID; p++) v[p] = 0.0f;

#pragma unroll 1
    for (int t = 0; t < TSTEPS; t++) {
        // Bulk-load this step's x (7 independent LDG.128 -> good MLP;
        // 8 lanes/sample share addresses -> coalescer dedups).
        float4 X[7];
#pragma unroll
        for (int q = 0; q < 7; q++) X[q] = xp[t * 7 + q];

        // 2-way split accumulators: chains of 18 instead of 36.
        u64 ijA = bIJ, ijB = pack2(0.0f);
        u64 foA = bFO, foB = pack2(0.0f);

        // rows 0..13 -> A chains, rows 14..27 -> B chains
#pragma unroll
        for (int ch = 0; ch < 7; ch++) {
#pragma unroll
            for (int j = 0; j < 4; j++) {
                float xs = (j == 0) ? X[ch].x : (j == 1) ? X[ch].y
                         : (j == 2) ? X[ch].z : X[ch].w;
                u64 xx = pack2(xs);
                const int k = 4 * ch + j;
                if (k < 14) {
                    ijA = fma2(xx, wXij[k], ijA);
                    foA = fma2(xx, wXfo[k], foA);
                } else {
                    ijB = fma2(xx, wXij[k], ijB);
                    foB = fma2(xx, wXfo[k], foB);
                }
            }
        }
        // h rows: 0..3 -> A, 4..7 -> B
#pragma unroll
        for (int p = 0; p < HID; p++) {
            u64 hh = pack2(v[p]);
            if (p < 4) {
                ijA = fma2(hh, wHij[p], ijA);
                foA = fma2(hh, wHfo[p], foA);
            } else {
                ijB = fma2(hh, wHij[p], ijB);
                foB = fma2(hh, wHfo[p], foB);
            }
        }

        u64 gij = add2(ijA, ijB);
        u64 gfo = add2(foA, foB);

        float gi, gj, gf, go;
        unpack2(gij, gi, gj);
        unpack2(gfo, gf, go);

        float ig = sigf(gi);
        float jt = tanh_exact(gj);
        float fg = sigf(gf);           // bias already folded in
        float og = sigf(go);
        c = c * fg + ig * jt;
        float h = tanh_exact(c) * og;

        // Flat all-gather: 7 independent shfls, depth 1.
        v[0] = h;
#pragma unroll
        for (int p = 1; p < HID; p++)
            v[p] = __shfl_xor_sync(0xffffffffu, h, p);
    }

    // Output projection: lane m==0 has v[p] = h[0^p] = h[p].
    if (m == 0) {
        float* op = out + (size_t)sample * NCLS;
#pragma unroll
        for (int n = 0; n < NCLS; n++) {
            float acc = sOB[n];
#pragma unroll
            for (int u = 0; u < HID; u++) acc += v[u] * sOW[u * NCLS + n];
            op[n] = acc;
        }
    }
}

extern "C" void kernel_launch(void* const* d_in, const int* in_sizes, int n_in,
                              void* d_out, int out_size) {
    const float* x  = (const float*)d_in[0];
    const float* W  = (const float*)d_in[1];
    const float* bl = (const float*)d_in[2];
    const float* ow = (const float*)d_in[3];
    const float* ob = (const float*)d_in[4];
    float* out = (float*)d_out;

    // 8 lanes per sample -> 262144 threads
    lstm_kernel<<<(BTOT * 8) / BLK, BLK>>>(x, W, bl, ow, ob, out);
}

// round 15
// speedup vs baseline: 1.0831x; 1.0831x over previous
#include <cuda_runtime.h>
#include <cuda_bf16.h>

// LSTM: B=32768, T=28, IN=28, H=8, NC=10. Gate order i,j,f,o. Forget bias 1.0.
// R14: ROW-PAIR f32x2 packing + 16 lanes/sample.
//  - f32x2 lanes = two adjacent x rows (x_{2r}, x_{2r+1}): operands come
//    straight from the ulonglong2 view of the x row -> ZERO pack/select
//    instructions (R12/R13 burned 36 packs/lane/step duplicating scalars).
//  - Weights pre-packed (w_{2r,c}, w_{2r+1,c}) at init; acc = (even,odd)
//    partial sums; one horizontal add per column per step.
//  - 16 lanes/sample: lane = unit m (bits 0-2) x gate-half hf (bit 3).
//    hf=0 owns columns {m, 8+m} (i,j); hf=1 owns {16+m, 24+m} (f,o).
//    72 weight regs/lane -> regs ~150, 16384 warps (work 27.7/SMSP).
//  - Activated-gate exchange via shfl.xor(8); both halves compute
//    bit-identical c,h; h all-gather = 7 flat shfls (order baked into wH).
//  - Exact activations (__expf + __fdividef). Forget bias folded at init.

#define BTOT 32768
#define TSTEPS 28
#define INDIM 28
#define HID 8
#define NCLS 10
#define BLK 128

typedef unsigned long long u64;

__device__ __forceinline__ u64 packab(float a, float b) {
    u64 r; unsigned ai = __float_as_uint(a), bi = __float_as_uint(b);
    asm("mov.b64 %0, {%1, %2};" : "=l"(r) : "r"(ai), "r"(bi));
    return r;
}

__device__ __forceinline__ u64 fma2(u64 a, u64 b, u64 c) {
    u64 d;
    asm("fma.rn.f32x2 %0, %1, %2, %3;" : "=l"(d) : "l"(a), "l"(b), "l"(c));
    return d;
}

__device__ __forceinline__ u64 add2(u64 a, u64 b) {
    u64 d;
    asm("add.rn.f32x2 %0, %1, %2;" : "=l"(d) : "l"(a), "l"(b));
    return d;
}

__device__ __forceinline__ void unpack2(u64 v, float& lo, float& hi) {
    unsigned a, b;
    asm("mov.b64 {%0, %1}, %2;" : "=r"(a), "=r"(b) : "l"(v));
    lo = __uint_as_float(a);
    hi = __uint_as_float(b);
}

__device__ __forceinline__ float sigf(float x) {
    float e = __expf(-x);
    return __fdividef(1.0f, 1.0f + e);
}

__device__ __forceinline__ float tanh_exact(float x) {
    // tanh(x) = 1 - 2/(e^{2x}+1). Overflow of e -> +1; underflow -> -1.
    float e = __expf(2.0f * x);
    return 1.0f - __fdividef(2.0f, e + 1.0f);
}

__global__ __launch_bounds__(BLK, 3)
void lstm_kernel(const float* __restrict__ x,
                 const float* __restrict__ W,      // [36, 32] row-major
                 const float* __restrict__ bias,   // [32]
                 const float* __restrict__ ow,     // [8, 10]
                 const float* __restrict__ ob,     // [10]
                 float* __restrict__ out)          // [B, 10]
{
    __shared__ float sWraw[(INDIM + HID) * 32];   // 36 x 32 staging
    __shared__ float sBr[32];
    __shared__ float sOW[HID * NCLS];
    __shared__ float sOB[NCLS];

    const int tid = threadIdx.x;
    for (int i = tid; i < (INDIM + HID) * 32; i += BLK) sWraw[i] = W[i];
    for (int i = tid; i < 32; i += BLK)          sBr[i] = bias[i];
    for (int i = tid; i < HID * NCLS; i += BLK)  sOW[i] = ow[i];
    for (int i = tid; i < NCLS; i += BLK)        sOB[i] = ob[i];
    __syncthreads();

    const int gtid   = blockIdx.x * BLK + tid;
    const int sample = gtid >> 4;          // 16 lanes per sample
    const int m      = gtid & 7;           // hidden unit
    const int hf     = (gtid >> 3) & 1;    // 0: i,j columns; 1: f,o columns

    const int c0 = hf * 16 + m;        // i or f column
    const int c1 = hf * 16 + 8 + m;    // j or o column

    // x-row-pair weights: wX*[r] = (W[2r][c], W[2r+1][c]) for r = 0..13
    u64 wX0[14], wX1[14];
#pragma unroll
    for (int r = 0; r < 14; r++) {
        wX0[r] = packab(sWraw[(2 * r) * 32 + c0], sWraw[(2 * r + 1) * 32 + c0]);
        wX1[r] = packab(sWraw[(2 * r) * 32 + c1], sWraw[(2 * r + 1) * 32 + c1]);
    }
    // h-row-pair weights in shfl-gather order: v[p] = h[m^p], pair r uses
    // (v[2r], v[2r+1]) -> rows (28 + (m^(2r)), 28 + (m^(2r+1))).
    u64 wH0[4], wH1[4];
#pragma unroll
    for (int r = 0; r < 4; r++) {
        const int ra = INDIM + (m ^ (2 * r));
        const int rb = INDIM + (m ^ (2 * r + 1));
        wH0[r] = packab(sWraw[ra * 32 + c0], sWraw[rb * 32 + c0]);
        wH1[r] = packab(sWraw[ra * 32 + c1], sWraw[rb * 32 + c1]);
    }
    const float b0 = sBr[c0] + (hf ? 1.0f : 0.0f);   // forget bias folded (c0=f when hf=1)
    const float b1 = sBr[c1];
    // tanh(x) for hf=0 (j), sigmoid(x) for hf=1 (o):  act1 = cB/(exp(kB*x)+1) + dB
    const float kB = hf ? -1.0f : 2.0f;
    const float cB = hf ?  1.0f : -2.0f;
    const float dB = hf ?  0.0f :  1.0f;

    const ulonglong2* xp = (const ulonglong2*)(x + (size_t)sample * TSTEPS * INDIM); // 7/step

    float c = 0.0f;
    u64 hp0 = 0, hp1 = 0, hp2 = 0, hp3 = 0;   // h pairs (v0,v1)..(v6,v7)
    float v[HID];
#pragma unroll
    for (int p = 0; p < HID; p++) v[p] = 0.0f;

#pragma unroll 1
    for (int t = 0; t < TSTEPS; t++) {
        // 7 LDG.128: x row = 14 u64 row-pairs, used as fma2 operands directly.
        ulonglong2 X[7];
#pragma unroll
        for (int q = 0; q < 7; q++) X[q] = xp[t * 7 + q];

        // 4 chains (2 per column), depth 9 each.
        u64 a0A = packab(b0, 0.0f), a0B = 0;
        u64 a1A = packab(b1, 0.0f), a1B = 0;

#pragma unroll
        for (int q = 0; q < 7; q++) {
            const u64 xlo = X[q].x, xhi = X[q].y;   // pairs 2q, 2q+1
            if (q < 4) {
                a0A = fma2(xlo, wX0[2 * q], a0A);
                a1A = fma2(xlo, wX1[2 * q], a1A);
            } else {
                a0B = fma2(xlo, wX0[2 * q], a0B);
                a1B = fma2(xlo, wX1[2 * q], a1B);
            }
            if (q < 3) {
                a0A = fma2(xhi, wX0[2 * q + 1], a0A);
                a1A = fma2(xhi, wX1[2 * q + 1], a1A);
            } else {
                a0B = fma2(xhi, wX0[2 * q + 1], a0B);
                a1B = fma2(xhi, wX1[2 * q + 1], a1B);
            }
        }
        // h pairs: 0,1 -> A chains; 2,3 -> B chains
        a0A = fma2(hp0, wH0[0], a0A);  a1A = fma2(hp0, wH1[0], a1A);
        a0A = fma2(hp1, wH0[1], a0A);  a1A = fma2(hp1, wH1[1], a1A);
        a0B = fma2(hp2, wH0[2], a0B);  a1B = fma2(hp2, wH1[2], a1B);
        a0B = fma2(hp3, wH0[3], a0B);  a1B = fma2(hp3, wH1[3], a1B);

        // merge + horizontal
        float lo0, hi0, lo1, hi1;
        unpack2(add2(a0A, a0B), lo0, hi0);
        unpack2(add2(a1A, a1B), lo1, hi1);
        const float g0 = lo0 + hi0;    // i (hf=0) or f+1 (hf=1)
        const float g1 = lo1 + hi1;    // j (hf=0) or o   (hf=1)

        // activations (uniform control flow)
        const float act0 = sigf(g0);                       // sigma(i) or sigma(f+1)
        const float eb   = __expf(kB * g1);
        const float act1 = cB * __fdividef(1.0f, eb + 1.0f) + dB;  // tanh(j) or sigma(o)

        // exchange with the other gate-half (lane xor 8)
        const float p0 = __shfl_xor_sync(0xffffffffu, act0, 8);
        const float p1 = __shfl_xor_sync(0xffffffffu, act1, 8);
        const float ig = hf ? p0 : act0;
        const float jt = hf ? p1 : act1;
        const float fg = hf ? act0 : p0;
        const float og = hf ? act1 : p1;

        c = c * fg + ig * jt;
        const float h = tanh_exact(c) * og;

        // flat all-gather: v[p] = h[m^p] (both halves identical)
        v[0] = h;
#pragma unroll
        for (int p = 1; p < HID; p++)
            v[p] = __shfl_xor_sync(0xffffffffu, h, p);

        hp0 = packab(v[0], v[1]);
        hp1 = packab(v[2], v[3]);
        hp2 = packab(v[4], v[5]);
        hp3 = packab(v[6], v[7]);
    }

    // Output projection: lane m==0, hf==0 has v[p] = h[p].
    if ((gtid & 15) == 0) {
        float* op = out + (size_t)sample * NCLS;
#pragma unroll
        for (int n = 0; n < NCLS; n++) {
            float acc = sOB[n];
#pragma unroll
            for (int u = 0; u < HID; u++) acc += v[u] * sOW[u * NCLS + n];
            op[n] = acc;
        }
    }
}

extern "C" void kernel_launch(void* const* d_in, const int* in_sizes, int n_in,
                              void* d_out, int out_size) {
    const float* x  = (const float*)d_in[0];
    const float* W  = (const float*)d_in[1];
    const float* bl = (const float*)d_in[2];
    const float* ow = (const float*)d_in[3];
    const float* ob = (const float*)d_in[4];
    float* out = (float*)d_out;

    // 16 lanes per sample -> 524288 threads
    lstm_kernel<<<(BTOT * 16) / BLK, BLK>>>(x, W, bl, ow, ob, out);
}

// round 16
// speedup vs baseline: 1.3246x; 1.2230x over previous
#include <cuda_runtime.h>
#include <cuda_bf16.h>

// LSTM: B=32768, T=28, IN=28, H=8, NC=10. Gate order i,j,f,o. Forget bias 1.0.
// R16: TWO-KERNEL SPLIT. Only h@Wh (8 of 36 rows) is recurrent; x@Wx (78% of
// FLOPs) is hoisted into a streaming GEMM:
//   gates_kernel: G[t][c][b] = x[b][t]@Wx + bias (+1 folded on f cols).
//                 Row-pair f32x2 (x pairs direct from LDG), 4 rows/thread
//                 (each weight LDS.64 feeds 4 fma2). Writes 117MB scratch.
//   recur_kernel: 8 lanes/sample, lane m = hidden unit m. Per step: 4
//                 coalesced LDG.32 of gates (prefetched one step ahead),
//                 16 fma2 (h@Wh, 32 weight regs), 5 exact activations,
//                 7 flat shfls (m^p order baked into weights at init).
// Scratch via static __device__ array (no allocation).

#define BTOT 32768
#define TSTEPS 28
#define INDIM 28
#define HID 8
#define NCLS 10
#define BLK 128

typedef unsigned long long u64;

__device__ float Gbuf[TSTEPS * 32 * BTOT];   // 117 MB gate scratch, [t][c][b]

__device__ __forceinline__ u64 pack2(float x) {
    u64 r; unsigned xi = __float_as_uint(x);
    asm("mov.b64 %0, {%1, %1};" : "=l"(r) : "r"(xi));
    return r;
}

__device__ __forceinline__ u64 packab(float a, float b) {
    u64 r; unsigned ai = __float_as_uint(a), bi = __float_as_uint(b);
    asm("mov.b64 %0, {%1, %2};" : "=l"(r) : "r"(ai), "r"(bi));
    return r;
}

__device__ __forceinline__ u64 fma2(u64 a, u64 b, u64 c) {
    u64 d;
    asm("fma.rn.f32x2 %0, %1, %2, %3;" : "=l"(d) : "l"(a), "l"(b), "l"(c));
    return d;
}

__device__ __forceinline__ void unpack2(u64 v, float& lo, float& hi) {
    unsigned a, b;
    asm("mov.b64 {%0, %1}, %2;" : "=r"(a), "=r"(b) : "l"(v));
    lo = __uint_as_float(a);
    hi = __uint_as_float(b);
}

__device__ __forceinline__ float sigf(float x) {
    float e = __expf(-x);
    return __fdividef(1.0f, 1.0f + e);
}

__device__ __forceinline__ float tanh_exact(float x) {
    // tanh(x) = 1 - 2/(e^{2x}+1). Overflow of e -> +1; underflow -> -1.
    float e = __expf(2.0f * x);
    return 1.0f - __fdividef(2.0f, e + 1.0f);
}

// ---------------- Kernel 1: input-gate GEMM --------------------------------
// Thread handles 4 consecutive timesteps of one sample (448B contiguous x).
// gtid: b = low 15 bits, tg = high bits (0..6).
__global__ __launch_bounds__(BLK)
void gates_kernel(const float* __restrict__ x,
                  const float* __restrict__ W,      // [36, 32] row-major
                  const float* __restrict__ bias)   // [32]
{
    __shared__ u64  sWrp[14 * 32];   // row-pair weights: (W[2kp][c], W[2kp+1][c])
    __shared__ float sBr[32];        // bias with forget fold

    const int tid = threadIdx.x;
    for (int i = tid; i < 14 * 32; i += BLK) {
        int kp = i >> 5, c = i & 31;
        sWrp[i] = packab(W[(2 * kp) * 32 + c], W[(2 * kp + 1) * 32 + c]);
    }
    for (int i = tid; i < 32; i += BLK)
        sBr[i] = bias[i] + ((i >= 16 && i < 24) ? 1.0f : 0.0f);   // forget bias
    __syncthreads();

    const int gtid = blockIdx.x * BLK + tid;
    const int b  = gtid & (BTOT - 1);
    const int tg = gtid >> 15;            // 0..6
    const int t0 = tg * 4;

    // Load this thread's 4 x rows (4 x 28 floats = 56 u64 row-pairs).
    const u64* xu = (const u64*)(x + (size_t)b * TSTEPS * INDIM + (size_t)t0 * INDIM);
    u64 X[56];
#pragma unroll
    for (int i = 0; i < 56; i++) X[i] = xu[i];

#pragma unroll 1
    for (int c = 0; c < 32; c++) {
        const u64 binit = packab(sBr[c], 0.0f);
        u64 a0 = binit, a1 = binit, a2 = binit, a3 = binit;
#pragma unroll
        for (int kp = 0; kp < 14; kp++) {
            const u64 w = sWrp[kp * 32 + c];
            a0 = fma2(X[kp],      w, a0);
            a1 = fma2(X[14 + kp], w, a1);
            a2 = fma2(X[28 + kp], w, a2);
            a3 = fma2(X[42 + kp], w, a3);
        }
        float lo, hi;
        unpack2(a0, lo, hi); Gbuf[(((t0 + 0) * 32 + c) << 15) + b] = lo + hi;
        unpack2(a1, lo, hi); Gbuf[(((t0 + 1) * 32 + c) << 15) + b] = lo + hi;
        unpack2(a2, lo, hi); Gbuf[(((t0 + 2) * 32 + c) << 15) + b] = lo + hi;
        unpack2(a3, lo, hi); Gbuf[(((t0 + 3) * 32 + c) << 15) + b] = lo + hi;
    }
}

// ---------------- Kernel 2: recurrence -------------------------------------
// 8 lanes per sample; lane m owns hidden unit m (gate cols m, 8+m, 16+m, 24+m).
__global__ __launch_bounds__(BLK)
void recur_kernel(const float* __restrict__ W,     // [36, 32] (rows 28..35 = Wh)
                  const float* __restrict__ ow,    // [8, 10]
                  const float* __restrict__ ob,    // [10]
                  float* __restrict__ out)         // [B, 10]
{
    __shared__ float sWh[HID * 32];   // h rows of W
    __shared__ float sOW[HID * NCLS];
    __shared__ float sOB[NCLS];

    const int tid = threadIdx.x;
    for (int i = tid; i < HID * 32; i += BLK)   sWh[i] = W[(INDIM + (i >> 5)) * 32 + (i & 31)];
    for (int i = tid; i < HID * NCLS; i += BLK) sOW[i] = ow[i];
    for (int i = tid; i < NCLS; i += BLK)       sOB[i] = ob[i];
    __syncthreads();

    const int gtid   = blockIdx.x * BLK + tid;
    const int sample = gtid >> 3;
    const int m      = gtid & 7;

    // h weights in shfl arrival order: position p delivers h[m^p].
    u64 wHij[HID], wHfo[HID];
#pragma unroll
    for (int p = 0; p < HID; p++) {
        const float* r = sWh + (m ^ p) * 32;
        wHij[p] = packab(r[m],      r[8 + m]);
        wHfo[p] = packab(r[16 + m], r[24 + m]);
    }

    float c = 0.0f;
    float v[HID];
#pragma unroll
    for (int p = 0; p < HID; p++) v[p] = 0.0f;

    // Prefetch step 0 gates (recurrence-independent loads).
    float gi = Gbuf[((0 * 32 + m)      << 15) + sample];
    float gj = Gbuf[((0 * 32 + 8 + m)  << 15) + sample];
    float gf = Gbuf[((0 * 32 + 16 + m) << 15) + sample];
    float go = Gbuf[((0 * 32 + 24 + m) << 15) + sample];

#pragma unroll 1
    for (int t = 0; t < TSTEPS; t++) {
        // software pipeline: issue next step's loads before this step's math
        const int tn = (t + 1 < TSTEPS) ? t + 1 : t;
        const float ngi = Gbuf[((tn * 32 + m)      << 15) + sample];
        const float ngj = Gbuf[((tn * 32 + 8 + m)  << 15) + sample];
        const float ngf = Gbuf[((tn * 32 + 16 + m) << 15) + sample];
        const float ngo = Gbuf[((tn * 32 + 24 + m) << 15) + sample];

        u64 aij = packab(gi, gj);
        u64 afo = packab(gf, go);
#pragma unroll
        for (int p = 0; p < HID; p++) {
            const u64 hh = pack2(v[p]);
            aij = fma2(hh, wHij[p], aij);
            afo = fma2(hh, wHfo[p], afo);
        }

        float zi, zj, zf, zo;
        unpack2(aij, zi, zj);
        unpack2(afo, zf, zo);

        const float ig = sigf(zi);
        const float jt = tanh_exact(zj);
        const float fg = sigf(zf);          // forget bias folded in kernel 1
        const float og = sigf(zo);
        c = c * fg + ig * jt;
        const float h = tanh_exact(c) * og;

        // flat all-gather: v[p] = h[m^p]
        v[0] = h;
#pragma unroll
        for (int p = 1; p < HID; p++)
            v[p] = __shfl_xor_sync(0xffffffffu, h, p);

        gi = ngi; gj = ngj; gf = ngf; go = ngo;
    }

    // Output projection: lane m==0 has v[p] = h[p].
    if (m == 0) {
        float* op = out + (size_t)sample * NCLS;
#pragma unroll
        for (int n = 0; n < NCLS; n++) {
            float acc = sOB[n];
#pragma unroll
            for (int u = 0; u < HID; u++) acc += v[u] * sOW[u * NCLS + n];
            op[n] = acc;
        }
    }
}

extern "C" void kernel_launch(void* const* d_in, const int* in_sizes, int n_in,
                              void* d_out, int out_size) {
    const float* x  = (const float*)d_in[0];
    const float* W  = (const float*)d_in[1];
    const float* bl = (const float*)d_in[2];
    const float* ow = (const float*)d_in[3];
    const float* ob = (const float*)d_in[4];
    float* out = (float*)d_out;

    // Kernel 1: B*T/4 threads (4 timesteps each)
    gates_kernel<<<(BTOT * TSTEPS / 4) / BLK, BLK>>>(x, W, bl);
    // Kernel 2: 8 lanes per sample
    recur_kernel<<<(BTOT * 8) / BLK, BLK>>>(W, ow, ob, out);
}